// round 15
// baseline (speedup 1.0000x reference)
#include <cuda_runtime.h>
#include <cuda_bf16.h>
#include <cstdint>

#define N_NODES  100000
#define N_PAD    100096            // 782 * 128
#define N_EDGES  600000
#define N_GRAPHS 2000
#define HID      128
#define LAYERS   6
#define SA       136               // bf16 row stride in smem (272 B)
#define NODES_PT 128               // nodes per tile (8 warps x 16 rows)
#define NT       (N_PAD / NODES_PT)  // 782 tiles
#define NBLK     148
#define GBLK     12500             // gather blocks (8 nodes each)
#define SCAN_B   1024
#define SCAN_NB  ((N_NODES + SCAN_B - 1) / SCAN_B)

// ---------------------------------------------------------------------------
// Persistent scratch (allocation-free). Ping-pong x buffers.
// ---------------------------------------------------------------------------
__device__ float g_xa[(size_t)N_NODES * HID];
__device__ float g_xb[(size_t)N_NODES * HID];
__device__ __align__(16) __nv_bfloat16 g_aggh[(size_t)N_PAD * HID];  // pad rows stay 0
__device__ __align__(16) __nv_bfloat16 g_aggl[(size_t)N_PAD * HID];
__device__ __align__(16) __nv_bfloat16 g_wt[(size_t)2 * 2 * LAYERS * HID * SA];
__device__ int g_flag[LAYERS * GBLK];   // per-gather-block done flags (zeroed each launch)
// CSR scratch
__device__ int g_deg[N_NODES];
__device__ int g_rowstart[N_NODES + 1];
__device__ int g_cursor[N_NODES];
__device__ int g_blocksum[SCAN_NB];
__device__ int g_csr[N_EDGES];

// ---------------------------------------------------------------------------
// helpers
// ---------------------------------------------------------------------------
__device__ __forceinline__ uint32_t smem_u32(const void* p) {
    uint32_t a;
    asm("{ .reg .u64 t; cvta.to.shared.u64 t, %1; cvt.u32.u64 %0, t; }"
        : "=r"(a) : "l"(p));
    return a;
}
__device__ __forceinline__ void ldm_x4(uint32_t (&r)[4], uint32_t addr) {
    asm volatile("ldmatrix.sync.aligned.m8n8.x4.shared.b16 {%0,%1,%2,%3}, [%4];"
                 : "=r"(r[0]), "=r"(r[1]), "=r"(r[2]), "=r"(r[3]) : "r"(addr));
}
__device__ __forceinline__ void mma16816(float (&d)[4], const uint32_t (&a)[4],
                                         uint32_t b0, uint32_t b1) {
    asm volatile(
        "mma.sync.aligned.m16n8k16.row.col.f32.bf16.bf16.f32 "
        "{%0,%1,%2,%3}, {%4,%5,%6,%7}, {%8,%9}, {%0,%1,%2,%3};"
        : "+f"(d[0]), "+f"(d[1]), "+f"(d[2]), "+f"(d[3])
        : "r"(a[0]), "r"(a[1]), "r"(a[2]), "r"(a[3]), "r"(b0), "r"(b1));
}
__device__ __forceinline__ uint32_t pk(__nv_bfloat16 a, __nv_bfloat16 b) {
    return (uint32_t)__bfloat16_as_ushort(a) |
           ((uint32_t)__bfloat16_as_ushort(b) << 16);
}
__device__ __forceinline__ int ld_acq(const int* p) {
    int v;
    asm volatile("ld.acquire.gpu.global.b32 %0, [%1];" : "=r"(v) : "l"(p) : "memory");
    return v;
}
__device__ __forceinline__ void red_release(int* p) {
    asm volatile("red.release.gpu.global.add.s32 [%0], %1;" :: "l"(p), "r"(1) : "memory");
}
#define CP16(dst, src) \
    asm volatile("cp.async.cg.shared.global [%0], [%1], 16;" \
                 :: "r"(dst), "l"(src) : "memory")
#define CP_COMMIT()  asm volatile("cp.async.commit_group;" ::: "memory")
#define CP_WAIT(n)   asm volatile("cp.async.wait_group %0;" :: "n"(n) : "memory")

// ---------------------------------------------------------------------------
// Embedding lookup -> g_xa; zeroes g_deg and the per-layer gather flags.
// ---------------------------------------------------------------------------
__global__ void embed_kernel(const int* __restrict__ tok,
                             const float* __restrict__ emb) {
    int i = blockIdx.x * blockDim.x + threadIdx.x;
    if (i >= N_NODES * 32) return;
    if (i < N_NODES) g_deg[i] = 0;
    if (i < LAYERS * GBLK) g_flag[i] = 0;
    int node = i >> 5, d = i & 31;
    ((float4*)g_xa)[i] = ((const float4*)emb)[tok[node] * 32 + d];
}

// ---------------------------------------------------------------------------
// CSR build
// ---------------------------------------------------------------------------
__global__ void k_hist(const int* __restrict__ ei) {
    int i = blockIdx.x * blockDim.x + threadIdx.x;
    if (i < N_EDGES) atomicAdd(&g_deg[ei[N_EDGES + i]], 1);
}
__global__ void k_scan1() {
    __shared__ int sm[SCAN_B];
    int tid = threadIdx.x;
    int i = blockIdx.x * SCAN_B + tid;
    int v = (i < N_NODES) ? g_deg[i] : 0;
    sm[tid] = v;
    __syncthreads();
#pragma unroll
    for (int o = 1; o < SCAN_B; o <<= 1) {
        int t = (tid >= o) ? sm[tid - o] : 0;
        __syncthreads();
        sm[tid] += t;
        __syncthreads();
    }
    if (i < N_NODES) g_rowstart[i] = sm[tid] - v;
    if (tid == SCAN_B - 1) g_blocksum[blockIdx.x] = sm[tid];
}
__global__ void k_scan2() {
    if (threadIdx.x == 0) {
        int run = 0;
        for (int b = 0; b < SCAN_NB; b++) {
            int t = g_blocksum[b];
            g_blocksum[b] = run;
            run += t;
        }
        g_rowstart[N_NODES] = run;
    }
}
__global__ void k_scan3() {
    int i = blockIdx.x * blockDim.x + threadIdx.x;
    if (i < N_NODES) {
        int r = g_rowstart[i] + g_blocksum[i / SCAN_B];
        g_rowstart[i] = r;
        g_cursor[i] = r;
    }
}
__global__ void k_fill(const int* __restrict__ ei) {
    int i = blockIdx.x * blockDim.x + threadIdx.x;
    if (i < N_EDGES) {
        int dst = ei[N_EDGES + i];
        g_csr[atomicAdd(&g_cursor[dst], 1)] = ei[i];
    }
}

// ---------------------------------------------------------------------------
// Gather for layer l: agg[n] = x_in[n] + sum_e x_in[csr[e]], split bf16 hi/lo.
// Block = 8 nodes (warp per node). Releases a per-block done flag.
// x_in = parity buffer (l even: g_xa, odd: g_xb).
// ---------------------------------------------------------------------------
__global__ void gather_kernel(int l) {
    const float* xin = (l & 1) ? g_xb : g_xa;
    int w = (blockIdx.x * blockDim.x + threadIdx.x) >> 5;
    int lane = threadIdx.x & 31;
    if (w < N_NODES) {
        int s = __ldg(g_rowstart + w), e = __ldg(g_rowstart + w + 1);
        const float4* x4 = (const float4*)xin;
        float4 v = x4[(size_t)w * 32 + lane];
        for (int i = s; i < e; i++) {
            int src = __ldg(g_csr + i);
            float4 u = x4[(size_t)src * 32 + lane];
            v.x += u.x; v.y += u.y; v.z += u.z; v.w += u.w;
        }
        __nv_bfloat16 h0 = __float2bfloat16(v.x), h1 = __float2bfloat16(v.y);
        __nv_bfloat16 h2 = __float2bfloat16(v.z), h3 = __float2bfloat16(v.w);
        __nv_bfloat16 l0 = __float2bfloat16(v.x - __bfloat162float(h0));
        __nv_bfloat16 l1 = __float2bfloat16(v.y - __bfloat162float(h1));
        __nv_bfloat16 l2 = __float2bfloat16(v.z - __bfloat162float(h2));
        __nv_bfloat16 l3 = __float2bfloat16(v.w - __bfloat162float(h3));
        size_t off = (size_t)w * HID + lane * 4;
        *(uint2*)(g_aggh + off) = make_uint2(pk(h0, h1), pk(h2, h3));
        *(uint2*)(g_aggl + off) = make_uint2(pk(l0, l1), pk(l2, l3));
    }
    __syncthreads();
    if (threadIdx.x == 0) {
        __threadfence();
        red_release(g_flag + l * GBLK + blockIdx.x);
    }
}

// ---------------------------------------------------------------------------
// Weight prep: split W[k][c] -> transposed hi/lo images Wt[c][k], stride SA.
// ---------------------------------------------------------------------------
__global__ void prep_w(const float* __restrict__ W1, const float* __restrict__ W2) {
    int i = blockIdx.x * blockDim.x + threadIdx.x;
    if (i >= 2 * LAYERS * HID * HID) return;
    int which = i / (LAYERS * HID * HID);
    int r = i % (LAYERS * HID * HID);
    int l = r / (HID * HID);
    int kc = r % (HID * HID);
    int k = kc / HID, c = kc % HID;
    const float* W = which ? W2 : W1;
    float v = W[(size_t)l * HID * HID + k * HID + c];
    __nv_bfloat16 hi = __float2bfloat16(v);
    __nv_bfloat16 lo = __float2bfloat16(v - __bfloat162float(hi));
    size_t img = (size_t)which * LAYERS + l;
    size_t o = img * HID * SA + (size_t)c * SA + k;
    g_wt[o] = hi;
    g_wt[(size_t)2 * LAYERS * HID * SA + o] = lo;
}

// ---------------------------------------------------------------------------
// Persistent register-fused GIN MLP (R14 structure) + per-tile flag waits so
// it can run CONCURRENTLY with gather of the same layer.
// ---------------------------------------------------------------------------
#define WTILE_B   (HID * SA * 2)            // 34816
#define AHALF_B   (NODES_PT * SA * 2)       // 34816 (128 rows)
#define BIAS_OFF  (4 * WTILE_B + 2 * AHALF_B)   // 208896
#define SMEM_BYTES (BIAS_OFF + 1024)            // 209920

__device__ __forceinline__ void prefetch_rows(uint32_t aA, int m0, int gnode0,
                                              int lane) {
#pragma unroll
    for (int i = 0; i < 16; i++) {
        int c = lane + 32 * i;        // 0..511
        int half = c >> 8;            // 0:hi 1:lo
        int r = (c >> 4) & 15;
        int o = c & 15;
        const __nv_bfloat16* src =
            (half ? g_aggl : g_aggh) + ((size_t)(gnode0 + r) << 7) + (o << 3);
        uint32_t dst = aA + half * AHALF_B + (m0 + r) * (SA * 2) + o * 16;
        CP16(dst, src);
    }
}

// wait until the 2 gather blocks covering this warp's 16 rows of tile t done
__device__ __forceinline__ void wait_tile(const int* flags, int t, int w, int lane) {
    if (lane == 0) {
        int b0 = t * 16 + 2 * w;
#pragma unroll
        for (int q = 0; q < 2; q++) {
            int b = b0 + q;
            if (b < GBLK) {
                while (ld_acq(flags + b) == 0) __nanosleep(64);
            }
        }
    }
    __syncwarp();
}

__global__ void __launch_bounds__(256, 1) mlp_mma(
    const float* __restrict__ b1, const float* __restrict__ b2, int l)
{
    extern __shared__ __align__(16) char S[];
    uint32_t base = smem_u32(S);
    uint32_t aW1h = base, aW1l = base + WTILE_B;
    uint32_t aW2h = base + 2 * WTILE_B, aW2l = base + 3 * WTILE_B;
    uint32_t aA = base + 4 * WTILE_B;      // hi; lo at +AHALF_B
    float* sbias = (float*)(S + BIAS_OFF); // [0:128) b1, [128:256) b2

    float* xout = (l & 1) ? g_xa : g_xb;
    const int* flags = g_flag + l * GBLK;

    int tid = threadIdx.x, warp = tid >> 5, lane = tid & 31;
    int bid = blockIdx.x;

    // ---- stage all weights + biases once ----
    {
        const size_t istr = (size_t)HID * SA;
        const size_t lstr = (size_t)2 * LAYERS * HID * SA;
        const float4* srcs[4] = {
            (const float4*)(g_wt + (size_t)l * istr),
            (const float4*)(g_wt + lstr + (size_t)l * istr),
            (const float4*)(g_wt + (size_t)(LAYERS + l) * istr),
            (const float4*)(g_wt + lstr + (size_t)(LAYERS + l) * istr) };
#pragma unroll
        for (int q = 0; q < 4; q++) {
            float4* d = (float4*)(S + q * WTILE_B);
            for (int i = tid; i < WTILE_B / 16; i += 256) d[i] = srcs[q][i];
        }
        if (tid < 128) sbias[tid] = __ldg(b1 + tid);
        else sbias[tid] = __ldg(b2 + tid - 128);
    }

    int m0 = warp * 16;
    int g = lane >> 3;
    int arow_off = (lane & 7) + ((g & 1) << 3);
    int akoff    = (g >> 1) << 3;
    int brow_off = (lane & 7) + ((g >> 1) << 3);
    int bkoff    = (g & 1) << 3;
    int cb = (lane & 3) * 2;
    int rA = m0 + (lane >> 2), rB = rA + 8;

    // first tile: wait for gather of our rows, then prefetch (warp-private)
    wait_tile(flags, bid, warp, lane);
    prefetch_rows(aA, m0, bid * NODES_PT + m0, lane);
    CP_COMMIT();
    __syncthreads();              // weights + biases visible to all

    for (int t = bid; t < NT; t += NBLK) {
        int node0 = t * NODES_PT;
        CP_WAIT(0);
        __syncwarp();

        // ================= GEMM 1 =================
        float acc[16][4];
#pragma unroll
        for (int n = 0; n < 16; n++)
#pragma unroll
            for (int c = 0; c < 4; c++) acc[n][c] = 0.f;

#pragma unroll
        for (int kb = 0; kb < 8; kb++) {
            uint32_t ah[4], al[4];
            uint32_t aro = (uint32_t)((m0 + arow_off) * SA + kb * 16 + akoff) * 2;
            ldm_x4(ah, aA + aro);
            ldm_x4(al, aA + AHALF_B + aro);
#pragma unroll
            for (int nb = 0; nb < 8; nb++) {
                uint32_t bh[4], bl[4];
                uint32_t ro = (uint32_t)((nb * 16 + brow_off) * SA + kb * 16 + bkoff) * 2;
                ldm_x4(bh, aW1h + ro);
                ldm_x4(bl, aW1l + ro);
                mma16816(acc[2 * nb],     ah, bh[0], bh[1]);
                mma16816(acc[2 * nb],     ah, bl[0], bl[1]);
                mma16816(acc[2 * nb],     al, bh[0], bh[1]);
                mma16816(acc[2 * nb + 1], ah, bh[2], bh[3]);
                mma16816(acc[2 * nb + 1], ah, bl[2], bl[3]);
                mma16816(acc[2 * nb + 1], al, bh[2], bh[3]);
            }
        }
        __syncwarp();
        // A slice consumed -> wait next tile's gather, then prefetch; the
        // load overlaps convert + GEMM2 + epilogue below.
        {
            int tn = t + NBLK;
            if (tn < NT) {
                wait_tile(flags, tn, warp, lane);
                prefetch_rows(aA, m0, tn * NODES_PT + m0, lane);
                CP_COMMIT();
            }
        }

        // ===== convert: H = relu(acc + b1) -> GEMM2 A fragments (regs) =====
        uint32_t ahi[8][4], alo[8][4];
#pragma unroll
        for (int j = 0; j < 8; j++) {
#pragma unroll
            for (int p = 0; p < 2; p++) {
                int nt = 2 * j + p;
                float bb0 = sbias[8 * nt + cb], bb1 = sbias[8 * nt + cb + 1];
                float v0 = fmaxf(acc[nt][0] + bb0, 0.f);
                float v1 = fmaxf(acc[nt][1] + bb1, 0.f);
                float v2 = fmaxf(acc[nt][2] + bb0, 0.f);
                float v3 = fmaxf(acc[nt][3] + bb1, 0.f);
                __nv_bfloat16 h0 = __float2bfloat16(v0), h1 = __float2bfloat16(v1);
                __nv_bfloat16 h2 = __float2bfloat16(v2), h3 = __float2bfloat16(v3);
                __nv_bfloat16 q0 = __float2bfloat16(v0 - __bfloat162float(h0));
                __nv_bfloat16 q1 = __float2bfloat16(v1 - __bfloat162float(h1));
                __nv_bfloat16 q2 = __float2bfloat16(v2 - __bfloat162float(h2));
                __nv_bfloat16 q3 = __float2bfloat16(v3 - __bfloat162float(h3));
                ahi[j][2 * p]     = pk(h0, h1);
                ahi[j][2 * p + 1] = pk(h2, h3);
                alo[j][2 * p]     = pk(q0, q1);
                alo[j][2 * p + 1] = pk(q2, q3);
            }
        }

        // ================= GEMM 2 (A from registers) =================
        float acc2[16][4];
#pragma unroll
        for (int n = 0; n < 16; n++)
#pragma unroll
            for (int c = 0; c < 4; c++) acc2[n][c] = 0.f;

#pragma unroll
        for (int kb = 0; kb < 8; kb++) {
#pragma unroll
            for (int nb = 0; nb < 8; nb++) {
                uint32_t bh[4], bl[4];
                uint32_t ro = (uint32_t)((nb * 16 + brow_off) * SA + kb * 16 + bkoff) * 2;
                ldm_x4(bh, aW2h + ro);
                ldm_x4(bl, aW2l + ro);
                mma16816(acc2[2 * nb],     ahi[kb], bh[0], bh[1]);
                mma16816(acc2[2 * nb],     ahi[kb], bl[0], bl[1]);
                mma16816(acc2[2 * nb],     alo[kb], bh[0], bh[1]);
                mma16816(acc2[2 * nb + 1], ahi[kb], bh[2], bh[3]);
                mma16816(acc2[2 * nb + 1], ahi[kb], bl[2], bl[3]);
                mma16816(acc2[2 * nb + 1], alo[kb], bh[2], bh[3]);
            }
        }

        // ============ epilogue: x_out = relu(acc2 + b2) ============
        {
            int gA = node0 + rA, gB = node0 + rB;
#pragma unroll
            for (int nt = 0; nt < 16; nt++) {
                int col = 8 * nt + cb;
                float bb0 = sbias[128 + col], bb1 = sbias[128 + col + 1];
                if (gA < N_NODES) {
                    float2 v = make_float2(fmaxf(acc2[nt][0] + bb0, 0.f),
                                           fmaxf(acc2[nt][1] + bb1, 0.f));
                    *(float2*)(xout + (size_t)gA * HID + col) = v;
                }
                if (gB < N_NODES) {
                    float2 v = make_float2(fmaxf(acc2[nt][2] + bb0, 0.f),
                                           fmaxf(acc2[nt][3] + bb1, 0.f));
                    *(float2*)(xout + (size_t)gB * HID + col) = v;
                }
            }
        }
    }
}

// ---------------------------------------------------------------------------
// Global mean pool (LAYERS even -> final x in g_xa)
// ---------------------------------------------------------------------------
__global__ void pool_kernel(const int* __restrict__ batch,
                            float* __restrict__ out) {
    int g = blockIdx.x;
    __shared__ int s_range[2];
    if (threadIdx.x == 0) {
        int lo = 0, hi = N_NODES;
        while (lo < hi) { int m = (lo + hi) >> 1; if (batch[m] < g) lo = m + 1; else hi = m; }
        s_range[0] = lo;
        lo = 0; hi = N_NODES;
        while (lo < hi) { int m = (lo + hi) >> 1; if (batch[m] < g + 1) lo = m + 1; else hi = m; }
        s_range[1] = lo;
    }
    __syncthreads();
    int start = s_range[0], end = s_range[1];
    float sum = 0.f;
    for (int n = start; n < end; n++)
        sum += g_xa[(size_t)n * HID + threadIdx.x];
    float cnt = (float)(end - start);
    out[g * HID + threadIdx.x] = sum / fmaxf(cnt, 1.0f);
}

// ---------------------------------------------------------------------------
// Inputs: x_tokens, edge_index, batch, emb, W1, b1, W2, b2
// Two-stream fork: gather_l runs concurrently with mlp_l (flag-synced).
// ---------------------------------------------------------------------------
extern "C" void kernel_launch(void* const* d_in, const int* in_sizes, int n_in,
                              void* d_out, int out_size) {
    const int*   tok   = (const int*)  d_in[0];
    const int*   ei    = (const int*)  d_in[1];
    const int*   batch = (const int*)  d_in[2];
    const float* emb   = (const float*)d_in[3];
    const float* W1    = (const float*)d_in[4];
    const float* b1    = (const float*)d_in[5];
    const float* W2    = (const float*)d_in[6];
    const float* b2    = (const float*)d_in[7];
    float* out = (float*)d_out;

    cudaFuncSetAttribute(mlp_mma, cudaFuncAttributeMaxDynamicSharedMemorySize,
                         SMEM_BYTES);

    static cudaStream_t s2 = nullptr;
    static cudaEvent_t evFork, evJoin, evM[LAYERS];
    if (!s2) {
        cudaStreamCreateWithFlags(&s2, cudaStreamNonBlocking);
        cudaEventCreateWithFlags(&evFork, cudaEventDisableTiming);
        cudaEventCreateWithFlags(&evJoin, cudaEventDisableTiming);
        for (int l = 0; l < LAYERS; l++)
            cudaEventCreateWithFlags(&evM[l], cudaEventDisableTiming);
    }

    prep_w<<<(2 * LAYERS * HID * HID + 255) / 256, 256>>>(W1, W2);
    embed_kernel<<<(N_NODES * 32 + 255) / 256, 256>>>(tok, emb);

    k_hist <<<(N_EDGES + 255) / 256, 256>>>(ei);
    k_scan1<<<SCAN_NB, SCAN_B>>>();
    k_scan2<<<1, 32>>>();
    k_scan3<<<(N_NODES + 255) / 256, 256>>>();
    k_fill <<<(N_EDGES + 255) / 256, 256>>>(ei);

    // fork: s2 starts after CSR + embed are done
    cudaEventRecord(evFork, 0);
    cudaStreamWaitEvent(s2, evFork, 0);

    for (int l = 0; l < LAYERS; l++) {
        gather_kernel<<<GBLK, 256, 0, s2>>>(l);            // concurrent with mlp_l
        mlp_mma<<<NBLK, 256, SMEM_BYTES>>>(                // main stream
            b1 + (size_t)l * HID, b2 + (size_t)l * HID, l);
        if (l + 1 < LAYERS) {
            cudaEventRecord(evM[l], 0);                    // after mlp_l
            cudaStreamWaitEvent(s2, evM[l], 0);            // gather_{l+1} waits x_{l+1}
        }
    }

    // join before pool
    cudaEventRecord(evJoin, s2);
    cudaStreamWaitEvent(0, evJoin, 0);

    pool_kernel<<<N_GRAPHS, HID>>>(batch, out);
}

// round 16
// speedup vs baseline: 1.0850x; 1.0850x over previous
#include <cuda_runtime.h>
#include <cuda_bf16.h>
#include <cstdint>

#define N_NODES  100000
#define N_PAD    100096            // 782 * 128
#define N_EDGES  600000
#define N_GRAPHS 2000
#define HID      128
#define LAYERS   6
#define SA       136               // bf16 row stride in smem (272 B)
#define NODES_PT 128               // nodes per tile (8 warps x 16 rows)
#define NT       (N_PAD / NODES_PT)  // 782 tiles
#define NBLK     148
#define SCAN_B   1024
#define SCAN_NB  ((N_NODES + SCAN_B - 1) / SCAN_B)

// ---------------------------------------------------------------------------
// Persistent scratch (allocation-free)
// ---------------------------------------------------------------------------
__device__ float g_x[(size_t)N_NODES * HID];
__device__ __align__(16) __nv_bfloat16 g_aggh[(size_t)N_PAD * HID];
__device__ __align__(16) __nv_bfloat16 g_aggl[(size_t)N_PAD * HID];
__device__ __align__(16) __nv_bfloat16 g_wt[(size_t)2 * 2 * LAYERS * HID * SA];
// CSR scratch
__device__ int g_deg[N_NODES];
__device__ int g_rowstart[N_NODES + 1];
__device__ int g_cursor[N_NODES];
__device__ int g_blocksum[SCAN_NB];
__device__ int g_csr[N_EDGES];

// ---------------------------------------------------------------------------
// helpers
// ---------------------------------------------------------------------------
__device__ __forceinline__ uint32_t smem_u32(const void* p) {
    uint32_t a;
    asm("{ .reg .u64 t; cvta.to.shared.u64 t, %1; cvt.u32.u64 %0, t; }"
        : "=r"(a) : "l"(p));
    return a;
}
__device__ __forceinline__ void ldm_x4(uint32_t (&r)[4], uint32_t addr) {
    asm volatile("ldmatrix.sync.aligned.m8n8.x4.shared.b16 {%0,%1,%2,%3}, [%4];"
                 : "=r"(r[0]), "=r"(r[1]), "=r"(r[2]), "=r"(r[3]) : "r"(addr));
}
__device__ __forceinline__ void mma16816(float (&d)[4], const uint32_t (&a)[4],
                                         uint32_t b0, uint32_t b1) {
    asm volatile(
        "mma.sync.aligned.m16n8k16.row.col.f32.bf16.bf16.f32 "
        "{%0,%1,%2,%3}, {%4,%5,%6,%7}, {%8,%9}, {%0,%1,%2,%3};"
        : "+f"(d[0]), "+f"(d[1]), "+f"(d[2]), "+f"(d[3])
        : "r"(a[0]), "r"(a[1]), "r"(a[2]), "r"(a[3]), "r"(b0), "r"(b1));
}
__device__ __forceinline__ uint32_t pk(__nv_bfloat16 a, __nv_bfloat16 b) {
    return (uint32_t)__bfloat16_as_ushort(a) |
           ((uint32_t)__bfloat16_as_ushort(b) << 16);
}
#define CP16(dst, src) \
    asm volatile("cp.async.cg.shared.global [%0], [%1], 16;" \
                 :: "r"(dst), "l"(src) : "memory")
#define CP_COMMIT()  asm volatile("cp.async.commit_group;" ::: "memory")
#define CP_WAIT(n)   asm volatile("cp.async.wait_group %0;" :: "n"(n) : "memory")

// ---------------------------------------------------------------------------
// Embedding lookup (also zeroes g_deg)
// ---------------------------------------------------------------------------
__global__ void embed_kernel(const int* __restrict__ tok,
                             const float* __restrict__ emb) {
    int i = blockIdx.x * blockDim.x + threadIdx.x;
    if (i >= N_NODES * 32) return;
    if (i < N_NODES) g_deg[i] = 0;
    int node = i >> 5, d = i & 31;
    ((float4*)g_x)[i] = ((const float4*)emb)[tok[node] * 32 + d];
}

// ---------------------------------------------------------------------------
// CSR build
// ---------------------------------------------------------------------------
__global__ void k_hist(const int* __restrict__ ei) {
    int i = blockIdx.x * blockDim.x + threadIdx.x;
    if (i < N_EDGES) atomicAdd(&g_deg[ei[N_EDGES + i]], 1);
}
__global__ void k_scan1() {
    __shared__ int sm[SCAN_B];
    int tid = threadIdx.x;
    int i = blockIdx.x * SCAN_B + tid;
    int v = (i < N_NODES) ? g_deg[i] : 0;
    sm[tid] = v;
    __syncthreads();
#pragma unroll
    for (int o = 1; o < SCAN_B; o <<= 1) {
        int t = (tid >= o) ? sm[tid - o] : 0;
        __syncthreads();
        sm[tid] += t;
        __syncthreads();
    }
    if (i < N_NODES) g_rowstart[i] = sm[tid] - v;
    if (tid == SCAN_B - 1) g_blocksum[blockIdx.x] = sm[tid];
}
__global__ void k_scan2() {
    if (threadIdx.x == 0) {
        int run = 0;
        for (int b = 0; b < SCAN_NB; b++) {
            int t = g_blocksum[b];
            g_blocksum[b] = run;
            run += t;
        }
        g_rowstart[N_NODES] = run;
    }
}
__global__ void k_scan3() {
    int i = blockIdx.x * blockDim.x + threadIdx.x;
    if (i < N_NODES) {
        int r = g_rowstart[i] + g_blocksum[i / SCAN_B];
        g_rowstart[i] = r;
        g_cursor[i] = r;
    }
}
__global__ void k_fill(const int* __restrict__ ei) {
    int i = blockIdx.x * blockDim.x + threadIdx.x;
    if (i < N_EDGES) {
        int dst = ei[N_EDGES + i];
        g_csr[atomicAdd(&g_cursor[dst], 1)] = ei[i];
    }
}

// ---------------------------------------------------------------------------
// Gather: agg[n] = x[n] + sum_e x[csr[e]]  (LTS-bound; simple loop)
// ---------------------------------------------------------------------------
__global__ void gather_kernel() {
    int w = (blockIdx.x * blockDim.x + threadIdx.x) >> 5;
    int lane = threadIdx.x & 31;
    if (w >= N_NODES) return;
    int s = __ldg(g_rowstart + w), e = __ldg(g_rowstart + w + 1);
    const float4* x4 = (const float4*)g_x;
    float4 v = x4[(size_t)w * 32 + lane];
    for (int i = s; i < e; i++) {
        int src = __ldg(g_csr + i);
        float4 u = x4[(size_t)src * 32 + lane];
        v.x += u.x; v.y += u.y; v.z += u.z; v.w += u.w;
    }
    __nv_bfloat16 h0 = __float2bfloat16(v.x), h1 = __float2bfloat16(v.y);
    __nv_bfloat16 h2 = __float2bfloat16(v.z), h3 = __float2bfloat16(v.w);
    __nv_bfloat16 l0 = __float2bfloat16(v.x - __bfloat162float(h0));
    __nv_bfloat16 l1 = __float2bfloat16(v.y - __bfloat162float(h1));
    __nv_bfloat16 l2 = __float2bfloat16(v.z - __bfloat162float(h2));
    __nv_bfloat16 l3 = __float2bfloat16(v.w - __bfloat162float(h3));
    size_t off = (size_t)w * HID + lane * 4;
    *(uint2*)(g_aggh + off) = make_uint2(pk(h0, h1), pk(h2, h3));
    *(uint2*)(g_aggl + off) = make_uint2(pk(l0, l1), pk(l2, l3));
}

// ---------------------------------------------------------------------------
// Weight prep
// ---------------------------------------------------------------------------
__global__ void prep_w(const float* __restrict__ W1, const float* __restrict__ W2) {
    int i = blockIdx.x * blockDim.x + threadIdx.x;
    if (i >= 2 * LAYERS * HID * HID) return;
    int which = i / (LAYERS * HID * HID);
    int r = i % (LAYERS * HID * HID);
    int l = r / (HID * HID);
    int kc = r % (HID * HID);
    int k = kc / HID, c = kc % HID;
    const float* W = which ? W2 : W1;
    float v = W[(size_t)l * HID * HID + k * HID + c];
    __nv_bfloat16 hi = __float2bfloat16(v);
    __nv_bfloat16 lo = __float2bfloat16(v - __bfloat162float(hi));
    size_t img = (size_t)which * LAYERS + l;
    size_t o = img * HID * SA + (size_t)c * SA + k;
    g_wt[o] = hi;
    g_wt[(size_t)2 * LAYERS * HID * SA + o] = lo;
}

// ---------------------------------------------------------------------------
// Persistent register-fused GIN MLP (R14) + software-pipelined fragment loads
// ---------------------------------------------------------------------------
#define WTILE_B   (HID * SA * 2)            // 34816
#define AHALF_B   (NODES_PT * SA * 2)       // 34816
#define BIAS_OFF  (4 * WTILE_B + 2 * AHALF_B)   // 208896
#define SMEM_BYTES (BIAS_OFF + 1024)            // 209920

__device__ __forceinline__ void prefetch_rows(uint32_t aA, int m0, int gnode0,
                                              int lane) {
#pragma unroll
    for (int i = 0; i < 16; i++) {
        int c = lane + 32 * i;
        int half = c >> 8;
        int r = (c >> 4) & 15;
        int o = c & 15;
        const __nv_bfloat16* src =
            (half ? g_aggl : g_aggh) + ((size_t)(gnode0 + r) << 7) + (o << 3);
        uint32_t dst = aA + half * AHALF_B + (m0 + r) * (SA * 2) + o * 16;
        CP16(dst, src);
    }
}

__global__ void __launch_bounds__(256, 1) mlp_mma(
    const float* __restrict__ b1, const float* __restrict__ b2, int l)
{
    extern __shared__ __align__(16) char S[];
    uint32_t base = smem_u32(S);
    uint32_t aW1h = base, aW1l = base + WTILE_B;
    uint32_t aW2h = base + 2 * WTILE_B, aW2l = base + 3 * WTILE_B;
    uint32_t aA = base + 4 * WTILE_B;
    float* sbias = (float*)(S + BIAS_OFF);

    int tid = threadIdx.x, warp = tid >> 5, lane = tid & 31;
    int bid = blockIdx.x;

    // ---- stage all weights + biases once ----
    {
        const size_t istr = (size_t)HID * SA;
        const size_t lstr = (size_t)2 * LAYERS * HID * SA;
        const float4* srcs[4] = {
            (const float4*)(g_wt + (size_t)l * istr),
            (const float4*)(g_wt + lstr + (size_t)l * istr),
            (const float4*)(g_wt + (size_t)(LAYERS + l) * istr),
            (const float4*)(g_wt + lstr + (size_t)(LAYERS + l) * istr) };
#pragma unroll
        for (int q = 0; q < 4; q++) {
            float4* d = (float4*)(S + q * WTILE_B);
            for (int i = tid; i < WTILE_B / 16; i += 256) d[i] = srcs[q][i];
        }
        if (tid < 128) sbias[tid] = __ldg(b1 + tid);
        else sbias[tid] = __ldg(b2 + tid - 128);
    }

    int m0 = warp * 16;
    int g = lane >> 3;
    int arow_off = (lane & 7) + ((g & 1) << 3);
    int akoff    = (g >> 1) << 3;
    int brow_off = (lane & 7) + ((g >> 1) << 3);
    int bkoff    = (g & 1) << 3;
    int cb = (lane & 3) * 2;
    int rA = m0 + (lane >> 2), rB = rA + 8;

    prefetch_rows(aA, m0, bid * NODES_PT + m0, lane);
    CP_COMMIT();
    __syncthreads();

    for (int t = bid; t < NT; t += NBLK) {
        int node0 = t * NODES_PT;
        CP_WAIT(0);
        __syncwarp();

        // ================= GEMM 1 (pipelined A and B frags) =================
        float acc[16][4];
#pragma unroll
        for (int n = 0; n < 16; n++)
#pragma unroll
            for (int c = 0; c < 4; c++) acc[n][c] = 0.f;

        {
            uint32_t ah[2][4], al[2][4], bh[2][4], bl[2][4];
            // initial A (kb=0) and B (kb=0, nb=0)
            {
                uint32_t ro = (uint32_t)((m0 + arow_off) * SA + akoff) * 2;
                ldm_x4(ah[0], aA + ro);
                ldm_x4(al[0], aA + AHALF_B + ro);
                uint32_t bo = (uint32_t)((brow_off) * SA + bkoff) * 2;
                ldm_x4(bh[0], aW1h + bo);
                ldm_x4(bl[0], aW1l + bo);
            }
#pragma unroll
            for (int kb = 0; kb < 8; kb++) {
                int pa = kb & 1;
#pragma unroll
                for (int nb = 0; nb < 8; nb++) {
                    int pb = nb & 1;
                    // prefetch next B fragment
                    int nk = (nb == 7) ? kb + 1 : kb;
                    int nn = (nb == 7) ? 0 : nb + 1;
                    if (nk < 8) {
                        uint32_t ro = (uint32_t)((nn * 16 + brow_off) * SA +
                                                 nk * 16 + bkoff) * 2;
                        ldm_x4(bh[1 - pb], aW1h + ro);
                        ldm_x4(bl[1 - pb], aW1l + ro);
                    }
                    // prefetch next A fragment mid-row
                    if (nb == 3 && kb < 7) {
                        uint32_t ro = (uint32_t)((m0 + arow_off) * SA +
                                                 (kb + 1) * 16 + akoff) * 2;
                        ldm_x4(ah[1 - pa], aA + ro);
                        ldm_x4(al[1 - pa], aA + AHALF_B + ro);
                    }
                    mma16816(acc[2 * nb],     ah[pa], bh[pb][0], bh[pb][1]);
                    mma16816(acc[2 * nb],     ah[pa], bl[pb][0], bl[pb][1]);
                    mma16816(acc[2 * nb],     al[pa], bh[pb][0], bh[pb][1]);
                    mma16816(acc[2 * nb + 1], ah[pa], bh[pb][2], bh[pb][3]);
                    mma16816(acc[2 * nb + 1], ah[pa], bl[pb][2], bl[pb][3]);
                    mma16816(acc[2 * nb + 1], al[pa], bh[pb][2], bh[pb][3]);
                }
            }
        }
        __syncwarp();
        // A slice consumed -> prefetch next tile (overlaps convert+GEMM2+epi)
        {
            int tn = t + NBLK;
            if (tn < NT) {
                prefetch_rows(aA, m0, tn * NODES_PT + m0, lane);
                CP_COMMIT();
            }
        }

        // ===== convert: H = relu(acc + b1) -> GEMM2 A fragments (regs) =====
        uint32_t ahi[8][4], alo[8][4];
#pragma unroll
        for (int j = 0; j < 8; j++) {
#pragma unroll
            for (int p = 0; p < 2; p++) {
                int nt = 2 * j + p;
                float bb0 = sbias[8 * nt + cb], bb1 = sbias[8 * nt + cb + 1];
                float v0 = fmaxf(acc[nt][0] + bb0, 0.f);
                float v1 = fmaxf(acc[nt][1] + bb1, 0.f);
                float v2 = fmaxf(acc[nt][2] + bb0, 0.f);
                float v3 = fmaxf(acc[nt][3] + bb1, 0.f);
                __nv_bfloat16 h0 = __float2bfloat16(v0), h1 = __float2bfloat16(v1);
                __nv_bfloat16 h2 = __float2bfloat16(v2), h3 = __float2bfloat16(v3);
                __nv_bfloat16 q0 = __float2bfloat16(v0 - __bfloat162float(h0));
                __nv_bfloat16 q1 = __float2bfloat16(v1 - __bfloat162float(h1));
                __nv_bfloat16 q2 = __float2bfloat16(v2 - __bfloat162float(h2));
                __nv_bfloat16 q3 = __float2bfloat16(v3 - __bfloat162float(h3));
                ahi[j][2 * p]     = pk(h0, h1);
                ahi[j][2 * p + 1] = pk(h2, h3);
                alo[j][2 * p]     = pk(q0, q1);
                alo[j][2 * p + 1] = pk(q2, q3);
            }
        }

        // ================= GEMM 2 (A in regs, B pipelined) =================
        float acc2[16][4];
#pragma unroll
        for (int n = 0; n < 16; n++)
#pragma unroll
            for (int c = 0; c < 4; c++) acc2[n][c] = 0.f;

        {
            uint32_t bh[2][4], bl[2][4];
            {
                uint32_t bo = (uint32_t)((brow_off) * SA + bkoff) * 2;
                ldm_x4(bh[0], aW2h + bo);
                ldm_x4(bl[0], aW2l + bo);
            }
#pragma unroll
            for (int kb = 0; kb < 8; kb++) {
#pragma unroll
                for (int nb = 0; nb < 8; nb++) {
                    int pb = nb & 1;
                    int nk = (nb == 7) ? kb + 1 : kb;
                    int nn = (nb == 7) ? 0 : nb + 1;
                    if (nk < 8) {
                        uint32_t ro = (uint32_t)((nn * 16 + brow_off) * SA +
                                                 nk * 16 + bkoff) * 2;
                        ldm_x4(bh[1 - pb], aW2h + ro);
                        ldm_x4(bl[1 - pb], aW2l + ro);
                    }
                    mma16816(acc2[2 * nb],     ahi[kb], bh[pb][0], bh[pb][1]);
                    mma16816(acc2[2 * nb],     ahi[kb], bl[pb][0], bl[pb][1]);
                    mma16816(acc2[2 * nb],     alo[kb], bh[pb][0], bh[pb][1]);
                    mma16816(acc2[2 * nb + 1], ahi[kb], bh[pb][2], bh[pb][3]);
                    mma16816(acc2[2 * nb + 1], ahi[kb], bl[pb][2], bl[pb][3]);
                    mma16816(acc2[2 * nb + 1], alo[kb], bh[pb][2], bh[pb][3]);
                }
            }
        }

        // ============ epilogue: x = relu(acc2 + b2) -> g_x ============
        {
            int gA = node0 + rA, gB = node0 + rB;
#pragma unroll
            for (int nt = 0; nt < 16; nt++) {
                int col = 8 * nt + cb;
                float bb0 = sbias[128 + col], bb1 = sbias[128 + col + 1];
                if (gA < N_NODES) {
                    float2 v = make_float2(fmaxf(acc2[nt][0] + bb0, 0.f),
                                           fmaxf(acc2[nt][1] + bb1, 0.f));
                    *(float2*)(g_x + (size_t)gA * HID + col) = v;
                }
                if (gB < N_NODES) {
                    float2 v = make_float2(fmaxf(acc2[nt][2] + bb0, 0.f),
                                           fmaxf(acc2[nt][3] + bb1, 0.f));
                    *(float2*)(g_x + (size_t)gB * HID + col) = v;
                }
            }
        }
    }
}

// ---------------------------------------------------------------------------
// Global mean pool
// ---------------------------------------------------------------------------
__global__ void pool_kernel(const int* __restrict__ batch,
                            float* __restrict__ out) {
    int g = blockIdx.x;
    __shared__ int s_range[2];
    if (threadIdx.x == 0) {
        int lo = 0, hi = N_NODES;
        while (lo < hi) { int m = (lo + hi) >> 1; if (batch[m] < g) lo = m + 1; else hi = m; }
        s_range[0] = lo;
        lo = 0; hi = N_NODES;
        while (lo < hi) { int m = (lo + hi) >> 1; if (batch[m] < g + 1) lo = m + 1; else hi = m; }
        s_range[1] = lo;
    }
    __syncthreads();
    int start = s_range[0], end = s_range[1];
    float sum = 0.f;
    for (int n = start; n < end; n++)
        sum += g_x[(size_t)n * HID + threadIdx.x];
    float cnt = (float)(end - start);
    out[g * HID + threadIdx.x] = sum / fmaxf(cnt, 1.0f);
}

// ---------------------------------------------------------------------------
// Inputs: x_tokens, edge_index, batch, emb, W1, b1, W2, b2
// ---------------------------------------------------------------------------
extern "C" void kernel_launch(void* const* d_in, const int* in_sizes, int n_in,
                              void* d_out, int out_size) {
    const int*   tok   = (const int*)  d_in[0];
    const int*   ei    = (const int*)  d_in[1];
    const int*   batch = (const int*)  d_in[2];
    const float* emb   = (const float*)d_in[3];
    const float* W1    = (const float*)d_in[4];
    const float* b1    = (const float*)d_in[5];
    const float* W2    = (const float*)d_in[6];
    const float* b2    = (const float*)d_in[7];
    float* out = (float*)d_out;

    cudaFuncSetAttribute(mlp_mma, cudaFuncAttributeMaxDynamicSharedMemorySize,
                         SMEM_BYTES);

    prep_w<<<(2 * LAYERS * HID * HID + 255) / 256, 256>>>(W1, W2);
    embed_kernel<<<(N_NODES * 32 + 255) / 256, 256>>>(tok, emb);

    k_hist <<<(N_EDGES + 255) / 256, 256>>>(ei);
    k_scan1<<<SCAN_NB, SCAN_B>>>();
    k_scan2<<<1, 32>>>();
    k_scan3<<<(N_NODES + 255) / 256, 256>>>();
    k_fill <<<(N_EDGES + 255) / 256, 256>>>(ei);

    for (int l = 0; l < LAYERS; l++) {
        gather_kernel<<<(N_NODES * 32 + 255) / 256, 256>>>();
        mlp_mma<<<NBLK, 256, SMEM_BYTES>>>(
            b1 + (size_t)l * HID, b2 + (size_t)l * HID, l);
    }

    pool_kernel<<<N_GRAPHS, HID>>>(batch, out);
}